// round 12
// baseline (speedup 1.0000x reference)
#include <cuda_runtime.h>
#include <cuda_bf16.h>
#include <math.h>
#include <cstdint>

#define L 8
#define E 8
#define R 64
#define H 2048
#define TOK 8192
#define SCALING 0.5f

#define TM 128
#define KSPLIT 8
#define KCH (H / KSPLIT)     // 256
#define BK 32
#define NC (KCH / BK)        // 8
#define NTILES (TOK / TM + E)

// aproj smem (bytes/stage): X rows 80B stride, A rows 80B stride; 2 stages
#define AP_XHI 0
#define AP_XLO 10240
#define AP_AHI 20480
#define AP_ALO 25600
#define AP_STG 30720
#define AP_TOT (2 * AP_STG)
// bproj smem: H rows 144B stride, B rows 144B stride
#define BP_HHI 0
#define BP_HLO 18432
#define BP_BHI 36864
#define BP_BLO 46080
#define BP_TOT 55296

#define NWA ((size_t)L * E * R * H)

typedef unsigned long long ull;

#define LDSM4(r, a) asm volatile( \
    "ldmatrix.sync.aligned.m8n8.x4.shared.b16 {%0,%1,%2,%3}, [%4];" \
    : "=r"((r)[0]), "=r"((r)[1]), "=r"((r)[2]), "=r"((r)[3]) : "r"(a))

#define MMA(d, a, b) asm volatile( \
    "mma.sync.aligned.m16n8k16.row.col.f32.bf16.bf16.f32 " \
    "{%0,%1,%2,%3},{%4,%5,%6,%7},{%8,%9},{%0,%1,%2,%3};" \
    : "+f"((d)[0]), "+f"((d)[1]), "+f"((d)[2]), "+f"((d)[3]) \
    : "r"((a)[0]), "r"((a)[1]), "r"((a)[2]), "r"((a)[3]), "r"((b)[0]), "r"((b)[1]))

#define CP16(d, s)  asm volatile("cp.async.cg.shared.global [%0], [%1], 16;" :: "r"(d), "l"(s))
#define CPCOMMIT()  asm volatile("cp.async.commit_group;" ::: "memory")
#define CPWAIT1()   asm volatile("cp.async.wait_group 1;" ::: "memory")
#define CPWAIT0()   asm volatile("cp.async.wait_group 0;" ::: "memory")

__device__ __forceinline__ uint32_t smem_u32(const void* p) {
    uint32_t a;
    asm("{.reg .u64 t; cvta.to.shared.u64 t, %1; cvt.u32.u64 %0, t;}" : "=r"(a) : "l"(p));
    return a;
}

__device__ __forceinline__ void cvt_split(float a, float b, uint32_t& hi, uint32_t& lo) {
    asm("cvt.rn.bf16x2.f32 %0, %1, %2;" : "=r"(hi) : "f"(b), "f"(a));
    float fa = __uint_as_float(hi << 16);
    float fb = __uint_as_float(hi & 0xFFFF0000u);
    float ra = a - fa, rb = b - fb;
    asm("cvt.rn.bf16x2.f32 %0, %1, %2;" : "=r"(lo) : "f"(rb), "f"(ra));
}

// ---------------- scratch ----------------------------------------------------
__device__ uint16_t g_xh[(size_t)TOK * H];
__device__ uint16_t g_xl[(size_t)TOK * H];
__device__ uint16_t g_ah[NWA], g_al[NWA];
__device__ uint16_t g_bh[NWA], g_bl[NWA];
__device__ float    g_hpart[KSPLIT][(size_t)TOK * R];
__device__ uint16_t g_hh[(size_t)TOK * R];
__device__ uint16_t g_hl[(size_t)TOK * R];
__device__ float    g_coef[TOK];
__device__ int      g_counts[E];
__device__ int      g_cnt[E];
__device__ int      g_tilestart[E + 1];
__device__ int      g_list[E * TOK];

// ---------------- prepass: weights f32 -> bf16 hi/lo --------------------------
__global__ void __launch_bounds__(256) wconv_kernel(const float* __restrict__ A,
                                                    const float* __restrict__ Bm)
{
    if (blockIdx.x == 0 && threadIdx.x < E) g_counts[threadIdx.x] = 0;
    size_t i = (size_t)blockIdx.x * 256 + threadIdx.x;
    const size_t NA4 = NWA / 4;
    const float4* src;
    uint16_t *hd, *ld;
    size_t j = i;
    if (i < NA4) { src = (const float4*)A;  hd = g_ah; ld = g_al; }
    else         { src = (const float4*)Bm; hd = g_bh; ld = g_bl; j = i - NA4; }
    float4 v = src[j];
    uint2 h, l;
    cvt_split(v.x, v.y, h.x, l.x);
    cvt_split(v.z, v.w, h.y, l.y);
    ((uint2*)hd)[j] = h;
    ((uint2*)ld)[j] = l;
}

__global__ void plan_kernel() {
    if (threadIdx.x == 0) {
        int ts = 0;
        for (int e = 0; e < E; e++) {
            int c = g_counts[e];
            g_cnt[e] = c;
            g_tilestart[e] = ts;
            g_counts[e] = 0;
            ts += (c + TM - 1) / TM;
        }
        g_tilestart[E] = ts;
    }
}

// ---------------- fused mix + gating + scatter --------------------------------
__global__ void __launch_bounds__(256) mix_gate_kernel(
    const float* __restrict__ xprev, const float* __restrict__ hx,
    const float* __restrict__ gw, const float* __restrict__ gates, int layer)
{
    int warp = threadIdx.x >> 5, lane = threadIdx.x & 31;
    int t = blockIdx.x * 8 + warp;

    float z = 1.0f / (1.0f + expf(-gates[layer]));
    float omz = 1.0f - z;

    const float* xp = xprev + (size_t)t * H;
    const float* hp = hx    + (size_t)t * H;
    uint32_t* xh32 = (uint32_t*)(g_xh + (size_t)t * H);
    uint32_t* xl32 = (uint32_t*)(g_xl + (size_t)t * H);

    float acc[E];
#pragma unroll
    for (int e = 0; e < E; e++) acc[e] = 0.f;

#pragma unroll 4
    for (int j = 0; j < H / 128; j++) {
        int k = j * 128 + lane * 4;
        float4 a = *(const float4*)(xp + k);
        float4 b = *(const float4*)(hp + k);
        float4 v;
        v.x = z * a.x + omz * b.x;
        v.y = z * a.y + omz * b.y;
        v.z = z * a.z + omz * b.z;
        v.w = z * a.w + omz * b.w;
        uint2 hh, ll;
        cvt_split(v.x, v.y, hh.x, ll.x);
        cvt_split(v.z, v.w, hh.y, ll.y);
        *(uint2*)(xh32 + k / 2) = hh;
        *(uint2*)(xl32 + k / 2) = ll;
#pragma unroll
        for (int e = 0; e < E; e++) {
            float4 w = *(const float4*)(gw + (size_t)e * H + k);
            acc[e] += v.x * w.x + v.y * w.y + v.z * w.z + v.w * w.w;
        }
    }
#pragma unroll
    for (int e = 0; e < E; e++)
#pragma unroll
        for (int o = 16; o > 0; o >>= 1)
            acc[e] += __shfl_xor_sync(0xffffffffu, acc[e], o);

    if (lane == 0) {
        float m = acc[0]; int g = 0;
#pragma unroll
        for (int e = 1; e < E; e++) if (acc[e] > m) { m = acc[e]; g = e; }
        float s = 0.f;
#pragma unroll
        for (int e = 0; e < E; e++) s += expf(acc[e] - m);
        g_coef[t] = SCALING / s;
        int pos = atomicAdd(&g_counts[g], 1);
        g_list[g * TOK + pos] = t;
    }
}

// ---------------- A projection: 256 threads, 2-stage cp.async, HMMA -----------
__global__ void __launch_bounds__(256) aproj_kernel(int layer)
{
    extern __shared__ __align__(16) char dsm[];
    __shared__ int s_tok[TM];

    int gt = blockIdx.x;
    if (gt >= g_tilestart[E]) return;
    int part = blockIdx.y;
    int e = 0;
    while (gt >= g_tilestart[e + 1]) e++;
    int tile = gt - g_tilestart[e];
    int cnt  = g_cnt[e];

    int tid = threadIdx.x, w = tid >> 5, lane = tid & 31;
    if (tid < TM) {
        int idx = tile * TM + tid;
        s_tok[tid] = (idx < cnt) ? g_list[e * TOK + idx] : -1;
    }
    __syncthreads();

    int xr = tid >> 1, xc = (tid & 1) << 4;
    int xtok = s_tok[xr];
    int cx = (xtok >= 0) ? xtok : s_tok[0];
    const uint16_t* xhs = g_xh + (size_t)cx * H + part * KCH + xc;
    const uint16_t* xls = g_xl + (size_t)cx * H + part * KCH + xc;
    int ar = tid >> 2, ac = (tid & 3) << 3;
    size_t aoff = (((size_t)layer * E + e) * R + ar) * H + part * KCH + ac;
    const uint16_t* ahs = g_ah + aoff;
    const uint16_t* als = g_al + aoff;

    uint32_t sb = smem_u32(dsm);
    uint32_t xhd = sb + AP_XHI + xr * 80 + xc * 2;
    uint32_t xld = sb + AP_XLO + xr * 80 + xc * 2;
    uint32_t ahd = sb + AP_AHI + ar * 80 + ac * 2;
    uint32_t ald = sb + AP_ALO + ar * 80 + ac * 2;

#define ASTAGE(kb, soff) do {                                  \
        CP16(xhd + (soff),      xhs + (kb));                   \
        CP16(xhd + (soff) + 16, xhs + (kb) + 8);               \
        CP16(xld + (soff),      xls + (kb));                   \
        CP16(xld + (soff) + 16, xls + (kb) + 8);               \
        CP16(ahd + (soff),      ahs + (kb));                   \
        CP16(ald + (soff),      als + (kb));                   \
        CPCOMMIT();                                            \
    } while (0)

    ASTAGE(0, 0);

    int rin = lane & 7;
    int xrow = w * 16 + ((lane >> 3) & 1) * 8 + rin;
    int xko  = ((lane >> 4) & 1) * 8;
    int brow0 = ((lane >> 4) & 1) * 8 + rin;
    int bko   = ((lane >> 3) & 1) * 8;

    float acc[8][4];
#pragma unroll
    for (int nt = 0; nt < 8; nt++)
#pragma unroll
        for (int q = 0; q < 4; q++) acc[nt][q] = 0.f;

#pragma unroll 1
    for (int kc = 0; kc < NC; kc++) {
        int nk = (kc + 1 < NC) ? (kc + 1) : (NC - 1);
        ASTAGE(nk * BK, ((kc + 1) & 1) * AP_STG);
        CPWAIT1();
        __syncthreads();

        uint32_t stg = sb + (kc & 1) * AP_STG;
#pragma unroll
        for (int kh = 0; kh < 2; kh++) {
            uint32_t xh[4], xl[4];
            uint32_t ro = (uint32_t)xrow * 80 + (kh * 16 + xko) * 2;
            LDSM4(xh, stg + AP_XHI + ro);
            LDSM4(xl, stg + AP_XLO + ro);
            uint32_t bh[8][2], bl[8][2];
#pragma unroll
            for (int nj = 0; nj < 4; nj++) {
                uint32_t bo = (uint32_t)(brow0 + nj * 16) * 80 + (kh * 16 + bko) * 2;
                uint32_t r[4];
                LDSM4(r, stg + AP_AHI + bo);
                bh[nj*2][0] = r[0]; bh[nj*2][1] = r[1];
                bh[nj*2+1][0] = r[2]; bh[nj*2+1][1] = r[3];
                LDSM4(r, stg + AP_ALO + bo);
                bl[nj*2][0] = r[0]; bl[nj*2][1] = r[1];
                bl[nj*2+1][0] = r[2]; bl[nj*2+1][1] = r[3];
            }
#pragma unroll
            for (int nt = 0; nt < 8; nt++) {
                MMA(acc[nt], xh, bh[nt]);
                MMA(acc[nt], xh, bl[nt]);
                MMA(acc[nt], xl, bh[nt]);
            }
        }
        __syncthreads();
    }
#undef ASTAGE

    float* hp = g_hpart[part];
    int mg = w * 16 + (lane >> 2);
    int t0 = s_tok[mg], t1 = s_tok[mg + 8];
#pragma unroll
    for (int nt = 0; nt < 8; nt++) {
        int n0 = nt * 8 + 2 * (lane & 3);
        if (t0 >= 0) *(float2*)&hp[(size_t)t0 * R + n0] = make_float2(acc[nt][0], acc[nt][1]);
        if (t1 >= 0) *(float2*)&hp[(size_t)t1 * R + n0] = make_float2(acc[nt][2], acc[nt][3]);
    }
}

// ---------------- reduce 8 partials -> bf16 hi/lo ------------------------------
__global__ void hreduce_kernel() {
    int i = blockIdx.x * 256 + threadIdx.x;
    float4 s0, s1;
    {
        float4 a = ((const float4*)g_hpart[0])[i];
        float4 b = ((const float4*)g_hpart[1])[i];
        float4 c = ((const float4*)g_hpart[2])[i];
        float4 d = ((const float4*)g_hpart[3])[i];
        s0.x = (a.x + b.x) + (c.x + d.x);
        s0.y = (a.y + b.y) + (c.y + d.y);
        s0.z = (a.z + b.z) + (c.z + d.z);
        s0.w = (a.w + b.w) + (c.w + d.w);
    }
    {
        float4 a = ((const float4*)g_hpart[4])[i];
        float4 b = ((const float4*)g_hpart[5])[i];
        float4 c = ((const float4*)g_hpart[6])[i];
        float4 d = ((const float4*)g_hpart[7])[i];
        s1.x = (a.x + b.x) + (c.x + d.x);
        s1.y = (a.y + b.y) + (c.y + d.y);
        s1.z = (a.z + b.z) + (c.z + d.z);
        s1.w = (a.w + b.w) + (c.w + d.w);
    }
    float4 o;
    o.x = s0.x + s1.x; o.y = s0.y + s1.y; o.z = s0.z + s1.z; o.w = s0.w + s1.w;
    uint2 h, l;
    cvt_split(o.x, o.y, h.x, l.x);
    cvt_split(o.z, o.w, h.y, l.y);
    ((uint2*)g_hh)[i] = h;
    ((uint2*)g_hl)[i] = l;
}

// ---------------- B projection: 256 threads, warp-M=16, HMMA -------------------
__global__ void __launch_bounds__(256, 3) bproj_kernel(int layer, float* __restrict__ y)
{
    extern __shared__ __align__(16) char dsm[];
    __shared__ int s_tok[TM];

    int gt = blockIdx.x;
    if (gt >= g_tilestart[E]) return;
    int e = 0;
    while (gt >= g_tilestart[e + 1]) e++;
    int tile = gt - g_tilestart[e];
    int cnt  = g_cnt[e];
    int h0   = blockIdx.y * 64;

    int tid = threadIdx.x, w = tid >> 5, lane = tid & 31;
    if (tid < TM) {
        int idx = tile * TM + tid;
        s_tok[tid] = (idx < cnt) ? g_list[e * TOK + idx] : -1;
    }
    __syncthreads();

    uint32_t sb = smem_u32(dsm);
    {
        int hr = tid >> 1, hc = (tid & 1) << 5;
        int htok = s_tok[hr];
        int ct = (htok >= 0) ? htok : s_tok[0];
        const uint16_t* hhs = g_hh + (size_t)ct * R + hc;
        const uint16_t* hls = g_hl + (size_t)ct * R + hc;
        uint32_t hhd = sb + BP_HHI + hr * 144 + hc * 2;
        uint32_t hld = sb + BP_HLO + hr * 144 + hc * 2;
#pragma unroll
        for (int q = 0; q < 4; q++) {
            CP16(hhd + q * 16, hhs + q * 8);
            CP16(hld + q * 16, hls + q * 8);
        }
        int br = tid >> 2, bc = (tid & 3) << 4;
        size_t boff = (((size_t)layer * E + e) * H + (size_t)(h0 + br)) * R + bc;
        const uint16_t* bhs = g_bh + boff;
        const uint16_t* bls = g_bl + boff;
        uint32_t bhd = sb + BP_BHI + br * 144 + bc * 2;
        uint32_t bld = sb + BP_BLO + br * 144 + bc * 2;
#pragma unroll
        for (int q = 0; q < 2; q++) {
            CP16(bhd + q * 16, bhs + q * 8);
            CP16(bld + q * 16, bls + q * 8);
        }
        CPCOMMIT();
        CPWAIT0();
    }
    __syncthreads();

    int rin = lane & 7;
    int xrow = w * 16 + ((lane >> 3) & 1) * 8 + rin;
    int xko  = ((lane >> 4) & 1) * 8;
    int brow0 = ((lane >> 4) & 1) * 8 + rin;
    int bko   = ((lane >> 3) & 1) * 8;

    float acc[8][4];
#pragma unroll
    for (int nt = 0; nt < 8; nt++)
#pragma unroll
        for (int q = 0; q < 4; q++) acc[nt][q] = 0.f;

#pragma unroll
    for (int kh = 0; kh < 4; kh++) {
        uint32_t xh[4], xl[4];
        uint32_t ro = (uint32_t)xrow * 144 + (kh * 16 + xko) * 2;
        LDSM4(xh, sb + BP_HHI + ro);
        LDSM4(xl, sb + BP_HLO + ro);
        uint32_t bh[8][2], bl[8][2];
#pragma unroll
        for (int nj = 0; nj < 4; nj++) {
            uint32_t bo = (uint32_t)(brow0 + nj * 16) * 144 + (kh * 16 + bko) * 2;
            uint32_t r[4];
            LDSM4(r, sb + BP_BHI + bo);
            bh[nj*2][0] = r[0]; bh[nj*2][1] = r[1];
            bh[nj*2+1][0] = r[2]; bh[nj*2+1][1] = r[3];
            LDSM4(r, sb + BP_BLO + bo);
            bl[nj*2][0] = r[0]; bl[nj*2][1] = r[1];
            bl[nj*2+1][0] = r[2]; bl[nj*2+1][1] = r[3];
        }
#pragma unroll
        for (int nt = 0; nt < 8; nt++) {
            MMA(acc[nt], xh, bh[nt]);
            MMA(acc[nt], xh, bl[nt]);
            MMA(acc[nt], xl, bh[nt]);
        }
    }

    int mg = w * 16 + (lane >> 2);
    int t0 = s_tok[mg], t1 = s_tok[mg + 8];
    float c0 = (t0 >= 0) ? g_coef[t0] : 0.f;
    float c1 = (t1 >= 0) ? g_coef[t1] : 0.f;
#pragma unroll
    for (int nt = 0; nt < 8; nt++) {
        int n0 = nt * 8 + 2 * (lane & 3);
        if (t0 >= 0)
            *(float2*)&y[(size_t)t0 * H + h0 + n0] =
                make_float2(acc[nt][0] * c0, acc[nt][1] * c0);
        if (t1 >= 0)
            *(float2*)&y[(size_t)t1 * H + h0 + n0] =
                make_float2(acc[nt][2] * c1, acc[nt][3] * c1);
    }
}

// ---------------- launcher ------------------------------------------------------
extern "C" void kernel_launch(void* const* d_in, const int* in_sizes, int n_in,
                              void* d_out, int out_size)
{
    const float* hs    = (const float*)d_in[0];
    const float* gates = (const float*)d_in[1];
    const float* A     = (const float*)d_in[2];
    const float* Bm    = (const float*)d_in[3];
    const float* gw    = (const float*)d_in[4];
    float* y = (float*)d_out;

    const size_t HS = (size_t)TOK * H;
    const int ASM = AP_TOT;         // 61440
    const int BSM = BP_TOT;         // 55296

    cudaFuncSetAttribute(aproj_kernel, cudaFuncAttributeMaxDynamicSharedMemorySize, ASM);
    cudaFuncSetAttribute(bproj_kernel, cudaFuncAttributeMaxDynamicSharedMemorySize, BSM);
    cudaFuncSetAttribute(aproj_kernel, cudaFuncAttributePreferredSharedMemoryCarveout, 100);
    cudaFuncSetAttribute(bproj_kernel, cudaFuncAttributePreferredSharedMemoryCarveout, 100);

    wconv_kernel<<<(int)(2 * NWA / 4 / 256), 256>>>(A, Bm);
    for (int i = 0; i < L; i++) {
        const float* xprev = (i == 0) ? hs : y;
        const float* hx    = hs + (size_t)((i == 0) ? 1 : i) * HS;

        mix_gate_kernel<<<TOK / 8, 256>>>(xprev, hx, gw + (size_t)i * E * H, gates, i);
        plan_kernel<<<1, 32>>>();
        aproj_kernel<<<dim3(NTILES, KSPLIT), 256, ASM>>>(i);
        hreduce_kernel<<<TOK * R / 4 / 256, 256>>>();
        bproj_kernel<<<dim3(NTILES, H / 64), 256, BSM>>>(i, y);
    }
}

// round 13
// speedup vs baseline: 1.0603x; 1.0603x over previous
#include <cuda_runtime.h>
#include <cuda_bf16.h>
#include <math.h>
#include <cstdint>

#define L 8
#define E 8
#define R 64
#define H 2048
#define TOK 8192
#define SCALING 0.5f

#define TM 128
#define KSPLIT 4
#define KCH (H / KSPLIT)     // 512
#define BK 32
#define NC (KCH / BK)        // 16
#define NTILES (TOK / TM + E)

// aproj smem (bytes/stage): X rows 80B stride, A rows 80B stride; 2 stages
#define AP_XHI 0
#define AP_XLO 10240
#define AP_AHI 20480
#define AP_ALO 25600
#define AP_STG 30720
#define AP_TOT (2 * AP_STG)

// bproj smem: H rows 144B stride (hi+lo), then 2 B buffers (hi+lo each)
#define NB 4
#define BPH_HI 0
#define BPH_LO 18432
#define BPB(buf) (36864 + (buf) * 18432)   // BHI at +0, BLO at +9216
#define BP_TOT 73728

#define NWA ((size_t)L * E * R * H)

typedef unsigned long long ull;

#define LDSM4(r, a) asm volatile( \
    "ldmatrix.sync.aligned.m8n8.x4.shared.b16 {%0,%1,%2,%3}, [%4];" \
    : "=r"((r)[0]), "=r"((r)[1]), "=r"((r)[2]), "=r"((r)[3]) : "r"(a))

#define MMA(d, a, b) asm volatile( \
    "mma.sync.aligned.m16n8k16.row.col.f32.bf16.bf16.f32 " \
    "{%0,%1,%2,%3},{%4,%5,%6,%7},{%8,%9},{%0,%1,%2,%3};" \
    : "+f"((d)[0]), "+f"((d)[1]), "+f"((d)[2]), "+f"((d)[3]) \
    : "r"((a)[0]), "r"((a)[1]), "r"((a)[2]), "r"((a)[3]), "r"((b)[0]), "r"((b)[1]))

#define CP16(d, s)  asm volatile("cp.async.cg.shared.global [%0], [%1], 16;" :: "r"(d), "l"(s))
#define CPCOMMIT()  asm volatile("cp.async.commit_group;" ::: "memory")
#define CPWAIT1()   asm volatile("cp.async.wait_group 1;" ::: "memory")

__device__ __forceinline__ uint32_t smem_u32(const void* p) {
    uint32_t a;
    asm("{.reg .u64 t; cvta.to.shared.u64 t, %1; cvt.u32.u64 %0, t;}" : "=r"(a) : "l"(p));
    return a;
}

__device__ __forceinline__ void cvt_split(float a, float b, uint32_t& hi, uint32_t& lo) {
    asm("cvt.rn.bf16x2.f32 %0, %1, %2;" : "=r"(hi) : "f"(b), "f"(a));
    float fa = __uint_as_float(hi << 16);
    float fb = __uint_as_float(hi & 0xFFFF0000u);
    float ra = a - fa, rb = b - fb;
    asm("cvt.rn.bf16x2.f32 %0, %1, %2;" : "=r"(lo) : "f"(rb), "f"(ra));
}

// ---------------- scratch ----------------------------------------------------
__device__ uint16_t g_xh[(size_t)TOK * H];
__device__ uint16_t g_xl[(size_t)TOK * H];
__device__ uint16_t g_ah[NWA], g_al[NWA];
__device__ uint16_t g_bh[NWA], g_bl[NWA];
__device__ float    g_hpart[KSPLIT][(size_t)TOK * R];
__device__ uint16_t g_hh[(size_t)TOK * R];
__device__ uint16_t g_hl[(size_t)TOK * R];
__device__ float    g_coef[TOK];
__device__ int      g_counts[E];
__device__ int      g_cnt[E];
__device__ int      g_tilestart[E + 1];
__device__ int      g_list[E * TOK];

// ---------------- prepass: weights f32 -> bf16 hi/lo --------------------------
__global__ void __launch_bounds__(256) wconv_kernel(const float* __restrict__ A,
                                                    const float* __restrict__ Bm)
{
    if (blockIdx.x == 0 && threadIdx.x < E) g_counts[threadIdx.x] = 0;
    size_t i = (size_t)blockIdx.x * 256 + threadIdx.x;
    const size_t NA4 = NWA / 4;
    const float4* src;
    uint16_t *hd, *ld;
    size_t j = i;
    if (i < NA4) { src = (const float4*)A;  hd = g_ah; ld = g_al; }
    else         { src = (const float4*)Bm; hd = g_bh; ld = g_bl; j = i - NA4; }
    float4 v = src[j];
    uint2 h, l;
    cvt_split(v.x, v.y, h.x, l.x);
    cvt_split(v.z, v.w, h.y, l.y);
    ((uint2*)hd)[j] = h;
    ((uint2*)ld)[j] = l;
}

__global__ void plan_kernel() {
    if (threadIdx.x == 0) {
        int ts = 0;
        for (int e = 0; e < E; e++) {
            int c = g_counts[e];
            g_cnt[e] = c;
            g_tilestart[e] = ts;
            g_counts[e] = 0;
            ts += (c + TM - 1) / TM;
        }
        g_tilestart[E] = ts;
    }
}

// ---------------- fused mix + gating + scatter --------------------------------
__global__ void __launch_bounds__(256) mix_gate_kernel(
    const float* __restrict__ xprev, const float* __restrict__ hx,
    const float* __restrict__ gw, const float* __restrict__ gates, int layer)
{
    int warp = threadIdx.x >> 5, lane = threadIdx.x & 31;
    int t = blockIdx.x * 8 + warp;

    float z = 1.0f / (1.0f + expf(-gates[layer]));
    float omz = 1.0f - z;

    const float* xp = xprev + (size_t)t * H;
    const float* hp = hx    + (size_t)t * H;
    uint32_t* xh32 = (uint32_t*)(g_xh + (size_t)t * H);
    uint32_t* xl32 = (uint32_t*)(g_xl + (size_t)t * H);

    float acc[E];
#pragma unroll
    for (int e = 0; e < E; e++) acc[e] = 0.f;

#pragma unroll 4
    for (int j = 0; j < H / 128; j++) {
        int k = j * 128 + lane * 4;
        float4 a = *(const float4*)(xp + k);
        float4 b = *(const float4*)(hp + k);
        float4 v;
        v.x = z * a.x + omz * b.x;
        v.y = z * a.y + omz * b.y;
        v.z = z * a.z + omz * b.z;
        v.w = z * a.w + omz * b.w;
        uint2 hh, ll;
        cvt_split(v.x, v.y, hh.x, ll.x);
        cvt_split(v.z, v.w, hh.y, ll.y);
        *(uint2*)(xh32 + k / 2) = hh;
        *(uint2*)(xl32 + k / 2) = ll;
#pragma unroll
        for (int e = 0; e < E; e++) {
            float4 w = *(const float4*)(gw + (size_t)e * H + k);
            acc[e] += v.x * w.x + v.y * w.y + v.z * w.z + v.w * w.w;
        }
    }
#pragma unroll
    for (int e = 0; e < E; e++)
#pragma unroll
        for (int o = 16; o > 0; o >>= 1)
            acc[e] += __shfl_xor_sync(0xffffffffu, acc[e], o);

    if (lane == 0) {
        float m = acc[0]; int g = 0;
#pragma unroll
        for (int e = 1; e < E; e++) if (acc[e] > m) { m = acc[e]; g = e; }
        float s = 0.f;
#pragma unroll
        for (int e = 0; e < E; e++) s += expf(acc[e] - m);
        g_coef[t] = SCALING / s;
        int pos = atomicAdd(&g_counts[g], 1);
        g_list[g * TOK + pos] = t;
    }
}

// ---------------- A projection: 256 threads, 2-stage cp.async, HMMA -----------
__global__ void __launch_bounds__(256) aproj_kernel(int layer)
{
    extern __shared__ __align__(16) char dsm[];
    __shared__ int s_tok[TM];

    int gt = blockIdx.x;
    if (gt >= g_tilestart[E]) return;
    int part = blockIdx.y;
    int e = 0;
    while (gt >= g_tilestart[e + 1]) e++;
    int tile = gt - g_tilestart[e];
    int cnt  = g_cnt[e];

    int tid = threadIdx.x, w = tid >> 5, lane = tid & 31;
    if (tid < TM) {
        int idx = tile * TM + tid;
        s_tok[tid] = (idx < cnt) ? g_list[e * TOK + idx] : -1;
    }
    __syncthreads();

    int xr = tid >> 1, xc = (tid & 1) << 4;
    int xtok = s_tok[xr];
    int cx = (xtok >= 0) ? xtok : s_tok[0];
    const uint16_t* xhs = g_xh + (size_t)cx * H + part * KCH + xc;
    const uint16_t* xls = g_xl + (size_t)cx * H + part * KCH + xc;
    int ar = tid >> 2, ac = (tid & 3) << 3;
    size_t aoff = (((size_t)layer * E + e) * R + ar) * H + part * KCH + ac;
    const uint16_t* ahs = g_ah + aoff;
    const uint16_t* als = g_al + aoff;

    uint32_t sb = smem_u32(dsm);
    uint32_t xhd = sb + AP_XHI + xr * 80 + xc * 2;
    uint32_t xld = sb + AP_XLO + xr * 80 + xc * 2;
    uint32_t ahd = sb + AP_AHI + ar * 80 + ac * 2;
    uint32_t ald = sb + AP_ALO + ar * 80 + ac * 2;

#define ASTAGE(kb, soff) do {                                  \
        CP16(xhd + (soff),      xhs + (kb));                   \
        CP16(xhd + (soff) + 16, xhs + (kb) + 8);               \
        CP16(xld + (soff),      xls + (kb));                   \
        CP16(xld + (soff) + 16, xls + (kb) + 8);               \
        CP16(ahd + (soff),      ahs + (kb));                   \
        CP16(ald + (soff),      als + (kb));                   \
        CPCOMMIT();                                            \
    } while (0)

    ASTAGE(0, 0);

    int rin = lane & 7;
    int xrow = w * 16 + ((lane >> 3) & 1) * 8 + rin;
    int xko  = ((lane >> 4) & 1) * 8;
    int brow0 = ((lane >> 4) & 1) * 8 + rin;
    int bko   = ((lane >> 3) & 1) * 8;

    float acc[8][4];
#pragma unroll
    for (int nt = 0; nt < 8; nt++)
#pragma unroll
        for (int q = 0; q < 4; q++) acc[nt][q] = 0.f;

#pragma unroll 1
    for (int kc = 0; kc < NC; kc++) {
        int nk = (kc + 1 < NC) ? (kc + 1) : (NC - 1);
        ASTAGE(nk * BK, ((kc + 1) & 1) * AP_STG);
        CPWAIT1();
        __syncthreads();

        uint32_t stg = sb + (kc & 1) * AP_STG;
#pragma unroll
        for (int kh = 0; kh < 2; kh++) {
            uint32_t xh[4], xl[4];
            uint32_t ro = (uint32_t)xrow * 80 + (kh * 16 + xko) * 2;
            LDSM4(xh, stg + AP_XHI + ro);
            LDSM4(xl, stg + AP_XLO + ro);
            uint32_t bh[8][2], bl[8][2];
#pragma unroll
            for (int nj = 0; nj < 4; nj++) {
                uint32_t bo = (uint32_t)(brow0 + nj * 16) * 80 + (kh * 16 + bko) * 2;
                uint32_t r[4];
                LDSM4(r, stg + AP_AHI + bo);
                bh[nj*2][0] = r[0]; bh[nj*2][1] = r[1];
                bh[nj*2+1][0] = r[2]; bh[nj*2+1][1] = r[3];
                LDSM4(r, stg + AP_ALO + bo);
                bl[nj*2][0] = r[0]; bl[nj*2][1] = r[1];
                bl[nj*2+1][0] = r[2]; bl[nj*2+1][1] = r[3];
            }
#pragma unroll
            for (int nt = 0; nt < 8; nt++) {
                MMA(acc[nt], xh, bh[nt]);
                MMA(acc[nt], xh, bl[nt]);
                MMA(acc[nt], xl, bh[nt]);
            }
        }
        __syncthreads();
    }
#undef ASTAGE

    float* hp = g_hpart[part];
    int mg = w * 16 + (lane >> 2);
    int t0 = s_tok[mg], t1 = s_tok[mg + 8];
#pragma unroll
    for (int nt = 0; nt < 8; nt++) {
        int n0 = nt * 8 + 2 * (lane & 3);
        if (t0 >= 0) *(float2*)&hp[(size_t)t0 * R + n0] = make_float2(acc[nt][0], acc[nt][1]);
        if (t1 >= 0) *(float2*)&hp[(size_t)t1 * R + n0] = make_float2(acc[nt][2], acc[nt][3]);
    }
}

// ---------------- reduce 4 partials -> bf16 hi/lo ------------------------------
__global__ void hreduce_kernel() {
    int i = blockIdx.x * 256 + threadIdx.x;
    float4 a = ((const float4*)g_hpart[0])[i];
    float4 b = ((const float4*)g_hpart[1])[i];
    float4 c = ((const float4*)g_hpart[2])[i];
    float4 d = ((const float4*)g_hpart[3])[i];
    float4 o;
    o.x = (a.x + b.x) + (c.x + d.x);
    o.y = (a.y + b.y) + (c.y + d.y);
    o.z = (a.z + b.z) + (c.z + d.z);
    o.w = (a.w + b.w) + (c.w + d.w);
    uint2 h, l;
    cvt_split(o.x, o.y, h.x, l.x);
    cvt_split(o.z, o.w, h.y, l.y);
    ((uint2*)g_hh)[i] = h;
    ((uint2*)g_hl)[i] = l;
}

// ---------------- B projection: NB=4 h0-blocks per CTA, HMMA -------------------
__global__ void __launch_bounds__(256) bproj_kernel(int layer, float* __restrict__ y)
{
    extern __shared__ __align__(16) char dsm[];
    __shared__ int s_tok[TM];

    int gt = blockIdx.x;
    if (gt >= g_tilestart[E]) return;
    int e = 0;
    while (gt >= g_tilestart[e + 1]) e++;
    int tile = gt - g_tilestart[e];
    int cnt  = g_cnt[e];
    int h0base = blockIdx.y * (64 * NB);

    int tid = threadIdx.x, w = tid >> 5, lane = tid & 31;
    if (tid < TM) {
        int idx = tile * TM + tid;
        s_tok[tid] = (idx < cnt) ? g_list[e * TOK + idx] : -1;
    }
    __syncthreads();

    uint32_t sb = smem_u32(dsm);

    // B staging addressing (reused per block)
    int br = tid >> 2, bc = (tid & 3) << 4;
    size_t bbase = (((size_t)layer * E + e) * H + (size_t)h0base + br) * R + bc;

#define BSTAGE(nb, buf) do {                                                   \
        const uint16_t* bhs = g_bh + bbase + (size_t)(nb) * 64 * R;            \
        const uint16_t* bls = g_bl + bbase + (size_t)(nb) * 64 * R;            \
        uint32_t bd = sb + BPB(buf) + br * 144 + bc * 2;                       \
        CP16(bd,          bhs);                                                \
        CP16(bd + 16,     bhs + 8);                                            \
        CP16(bd + 9216,      bls);                                             \
        CP16(bd + 9216 + 16, bls + 8);                                         \
    } while (0)

    // stage H (once) + B block 0 -> group 0
    {
        int hr = tid >> 1, hc = (tid & 1) << 5;
        int htok = s_tok[hr];
        int ct = (htok >= 0) ? htok : s_tok[0];
        const uint16_t* hhs = g_hh + (size_t)ct * R + hc;
        const uint16_t* hls = g_hl + (size_t)ct * R + hc;
        uint32_t hhd = sb + BPH_HI + hr * 144 + hc * 2;
        uint32_t hld = sb + BPH_LO + hr * 144 + hc * 2;
#pragma unroll
        for (int q = 0; q < 4; q++) {
            CP16(hhd + q * 16, hhs + q * 8);
            CP16(hld + q * 16, hls + q * 8);
        }
        BSTAGE(0, 0);
        CPCOMMIT();
    }

    int rin = lane & 7;
    int xrow = w * 16 + ((lane >> 3) & 1) * 8 + rin;
    int xko  = ((lane >> 4) & 1) * 8;
    int brow0 = ((lane >> 4) & 1) * 8 + rin;
    int bko   = ((lane >> 3) & 1) * 8;

    int mg = w * 16 + (lane >> 2);
    int t0 = s_tok[mg], t1 = s_tok[mg + 8];
    float c0 = (t0 >= 0) ? g_coef[t0] : 0.f;
    float c1 = (t1 >= 0) ? g_coef[t1] : 0.f;

#pragma unroll 1
    for (int nb = 0; nb < NB; nb++) {
        if (nb + 1 < NB) BSTAGE(nb + 1, (nb + 1) & 1);
        CPCOMMIT();
        CPWAIT1();
        __syncthreads();

        uint32_t bbuf = sb + BPB(nb & 1);

        float acc[8][4];
#pragma unroll
        for (int nt = 0; nt < 8; nt++)
#pragma unroll
            for (int q = 0; q < 4; q++) acc[nt][q] = 0.f;

#pragma unroll
        for (int kh = 0; kh < 4; kh++) {
            uint32_t xh[4], xl[4];
            uint32_t ro = (uint32_t)xrow * 144 + (kh * 16 + xko) * 2;
            LDSM4(xh, sb + BPH_HI + ro);
            LDSM4(xl, sb + BPH_LO + ro);
            uint32_t bh[8][2], bl[8][2];
#pragma unroll
            for (int nj = 0; nj < 4; nj++) {
                uint32_t bo = (uint32_t)(brow0 + nj * 16) * 144 + (kh * 16 + bko) * 2;
                uint32_t r[4];
                LDSM4(r, bbuf + bo);
                bh[nj*2][0] = r[0]; bh[nj*2][1] = r[1];
                bh[nj*2+1][0] = r[2]; bh[nj*2+1][1] = r[3];
                LDSM4(r, bbuf + 9216 + bo);
                bl[nj*2][0] = r[0]; bl[nj*2][1] = r[1];
                bl[nj*2+1][0] = r[2]; bl[nj*2+1][1] = r[3];
            }
#pragma unroll
            for (int nt = 0; nt < 8; nt++) {
                MMA(acc[nt], xh, bh[nt]);
                MMA(acc[nt], xh, bl[nt]);
                MMA(acc[nt], xl, bh[nt]);
            }
        }

        int h0 = h0base + nb * 64;
#pragma unroll
        for (int nt = 0; nt < 8; nt++) {
            int n0 = nt * 8 + 2 * (lane & 3);
            if (t0 >= 0)
                *(float2*)&y[(size_t)t0 * H + h0 + n0] =
                    make_float2(acc[nt][0] * c0, acc[nt][1] * c0);
            if (t1 >= 0)
                *(float2*)&y[(size_t)t1 * H + h0 + n0] =
                    make_float2(acc[nt][2] * c1, acc[nt][3] * c1);
        }
        __syncthreads();
    }
#undef BSTAGE
}

// ---------------- launcher ------------------------------------------------------
extern "C" void kernel_launch(void* const* d_in, const int* in_sizes, int n_in,
                              void* d_out, int out_size)
{
    const float* hs    = (const float*)d_in[0];
    const float* gates = (const float*)d_in[1];
    const float* A     = (const float*)d_in[2];
    const float* Bm    = (const float*)d_in[3];
    const float* gw    = (const float*)d_in[4];
    float* y = (float*)d_out;

    const size_t HS = (size_t)TOK * H;
    const int ASM = AP_TOT;         // 61440
    const int BSM = BP_TOT;         // 73728

    cudaFuncSetAttribute(aproj_kernel, cudaFuncAttributeMaxDynamicSharedMemorySize, ASM);
    cudaFuncSetAttribute(bproj_kernel, cudaFuncAttributeMaxDynamicSharedMemorySize, BSM);
    cudaFuncSetAttribute(aproj_kernel, cudaFuncAttributePreferredSharedMemoryCarveout, 100);
    cudaFuncSetAttribute(bproj_kernel, cudaFuncAttributePreferredSharedMemoryCarveout, 100);

    wconv_kernel<<<(int)(2 * NWA / 4 / 256), 256>>>(A, Bm);
    for (int i = 0; i < L; i++) {
        const float* xprev = (i == 0) ? hs : y;
        const float* hx    = hs + (size_t)((i == 0) ? 1 : i) * HS;

        mix_gate_kernel<<<TOK / 8, 256>>>(xprev, hx, gw + (size_t)i * E * H, gates, i);
        plan_kernel<<<1, 32>>>();
        aproj_kernel<<<dim3(NTILES, KSPLIT), 256, ASM>>>(i);
        hreduce_kernel<<<TOK * R / 4 / 256, 256>>>();
        bproj_kernel<<<dim3(NTILES, H / (64 * NB)), 256, BSM>>>(i, y);
    }
}

// round 14
// speedup vs baseline: 1.1042x; 1.0414x over previous
#include <cuda_runtime.h>
#include <cuda_bf16.h>
#include <math.h>
#include <cstdint>

#define L 8
#define E 8
#define R 64
#define H 2048
#define TOK 8192
#define SCALING 0.5f

#define TM 128
#define KSPLIT 4
#define KCH (H / KSPLIT)     // 512
#define BK 32
#define NC (KCH / BK)        // 16
#define NTILES (TOK / TM + E)

// aproj smem (bytes/stage): X rows 80B stride, A rows 80B stride; 3 stages
#define AP_XHI 0
#define AP_XLO 10240
#define AP_AHI 20480
#define AP_ALO 25600
#define AP_STG 30720
#define AP_TOT (3 * AP_STG)   // 92160

// bproj smem: H rows 144B stride (hi+lo), then 3 B buffers (hi 9216 + lo 9216)
#define NB 8
#define BPH_HI 0
#define BPH_LO 18432
#define BPB(buf) (36864 + (buf) * 18432)
#define BP_TOT (36864 + 3 * 18432)   // 92160

#define NWA ((size_t)L * E * R * H)

typedef unsigned long long ull;

#define LDSM4(r, a) asm volatile( \
    "ldmatrix.sync.aligned.m8n8.x4.shared.b16 {%0,%1,%2,%3}, [%4];" \
    : "=r"((r)[0]), "=r"((r)[1]), "=r"((r)[2]), "=r"((r)[3]) : "r"(a))

#define MMA(d, a, b) asm volatile( \
    "mma.sync.aligned.m16n8k16.row.col.f32.bf16.bf16.f32 " \
    "{%0,%1,%2,%3},{%4,%5,%6,%7},{%8,%9},{%0,%1,%2,%3};" \
    : "+f"((d)[0]), "+f"((d)[1]), "+f"((d)[2]), "+f"((d)[3]) \
    : "r"((a)[0]), "r"((a)[1]), "r"((a)[2]), "r"((a)[3]), "r"((b)[0]), "r"((b)[1]))

#define CP16(d, s)  asm volatile("cp.async.cg.shared.global [%0], [%1], 16;" :: "r"(d), "l"(s))
#define CPCOMMIT()  asm volatile("cp.async.commit_group;" ::: "memory")
#define CPWAIT1()   asm volatile("cp.async.wait_group 1;" ::: "memory")

__device__ __forceinline__ uint32_t smem_u32(const void* p) {
    uint32_t a;
    asm("{.reg .u64 t; cvta.to.shared.u64 t, %1; cvt.u32.u64 %0, t;}" : "=r"(a) : "l"(p));
    return a;
}

__device__ __forceinline__ void cvt_split(float a, float b, uint32_t& hi, uint32_t& lo) {
    asm("cvt.rn.bf16x2.f32 %0, %1, %2;" : "=r"(hi) : "f"(b), "f"(a));
    float fa = __uint_as_float(hi << 16);
    float fb = __uint_as_float(hi & 0xFFFF0000u);
    float ra = a - fa, rb = b - fb;
    asm("cvt.rn.bf16x2.f32 %0, %1, %2;" : "=r"(lo) : "f"(rb), "f"(ra));
}

// ---------------- scratch ----------------------------------------------------
__device__ uint16_t g_xh[(size_t)TOK * H];
__device__ uint16_t g_xl[(size_t)TOK * H];
__device__ uint16_t g_ah[NWA], g_al[NWA];
__device__ uint16_t g_bh[NWA], g_bl[NWA];
__device__ float    g_hpart[KSPLIT][(size_t)TOK * R];
__device__ uint16_t g_hh[(size_t)TOK * R];
__device__ uint16_t g_hl[(size_t)TOK * R];
__device__ float    g_coef[TOK];
__device__ int      g_counts[2][E];     // double-buffered by layer parity
__device__ int      g_list[E * TOK];

// ---------------- prepass: weights f32 -> bf16 hi/lo --------------------------
__global__ void __launch_bounds__(256) wconv_kernel(const float* __restrict__ A,
                                                    const float* __restrict__ Bm)
{
    if (blockIdx.x == 0 && threadIdx.x < 2 * E)
        g_counts[threadIdx.x >> 3][threadIdx.x & 7] = 0;
    size_t i = (size_t)blockIdx.x * 256 + threadIdx.x;
    const size_t NA4 = NWA / 4;
    const float4* src;
    uint16_t *hd, *ld;
    size_t j = i;
    if (i < NA4) { src = (const float4*)A;  hd = g_ah; ld = g_al; }
    else         { src = (const float4*)Bm; hd = g_bh; ld = g_bl; j = i - NA4; }
    float4 v = src[j];
    uint2 h, l;
    cvt_split(v.x, v.y, h.x, l.x);
    cvt_split(v.z, v.w, h.y, l.y);
    ((uint2*)hd)[j] = h;
    ((uint2*)ld)[j] = l;
}

// ---------------- fused mix + gating + scatter --------------------------------
__global__ void __launch_bounds__(256) mix_gate_kernel(
    const float* __restrict__ xprev, const float* __restrict__ hx,
    const float* __restrict__ gw, const float* __restrict__ gates, int layer)
{
    // zero the NEXT layer's count buffer (its previous consumers are done)
    if (blockIdx.x == 0 && threadIdx.x < E)
        g_counts[(layer + 1) & 1][threadIdx.x] = 0;

    int warp = threadIdx.x >> 5, lane = threadIdx.x & 31;
    int t = blockIdx.x * 8 + warp;

    float z = 1.0f / (1.0f + expf(-gates[layer]));
    float omz = 1.0f - z;

    const float* xp = xprev + (size_t)t * H;
    const float* hp = hx    + (size_t)t * H;
    uint32_t* xh32 = (uint32_t*)(g_xh + (size_t)t * H);
    uint32_t* xl32 = (uint32_t*)(g_xl + (size_t)t * H);

    float acc[E];
#pragma unroll
    for (int e = 0; e < E; e++) acc[e] = 0.f;

#pragma unroll 4
    for (int j = 0; j < H / 128; j++) {
        int k = j * 128 + lane * 4;
        float4 a = *(const float4*)(xp + k);
        float4 b = *(const float4*)(hp + k);
        float4 v;
        v.x = z * a.x + omz * b.x;
        v.y = z * a.y + omz * b.y;
        v.z = z * a.z + omz * b.z;
        v.w = z * a.w + omz * b.w;
        uint2 hh, ll;
        cvt_split(v.x, v.y, hh.x, ll.x);
        cvt_split(v.z, v.w, hh.y, ll.y);
        *(uint2*)(xh32 + k / 2) = hh;
        *(uint2*)(xl32 + k / 2) = ll;
#pragma unroll
        for (int e = 0; e < E; e++) {
            float4 w = *(const float4*)(gw + (size_t)e * H + k);
            acc[e] += v.x * w.x + v.y * w.y + v.z * w.z + v.w * w.w;
        }
    }
#pragma unroll
    for (int e = 0; e < E; e++)
#pragma unroll
        for (int o = 16; o > 0; o >>= 1)
            acc[e] += __shfl_xor_sync(0xffffffffu, acc[e], o);

    if (lane == 0) {
        float m = acc[0]; int g = 0;
#pragma unroll
        for (int e = 1; e < E; e++) if (acc[e] > m) { m = acc[e]; g = e; }
        float s = 0.f;
#pragma unroll
        for (int e = 0; e < E; e++) s += expf(acc[e] - m);
        g_coef[t] = SCALING / s;
        int pos = atomicAdd(&g_counts[layer & 1][g], 1);
        g_list[g * TOK + pos] = t;
    }
}

// ---------------- A projection: 3-stage single-sync cp.async + HMMA -----------
__global__ void __launch_bounds__(256) aproj_kernel(int layer)
{
    extern __shared__ __align__(16) char dsm[];
    __shared__ int s_tok[TM];
    __shared__ int s_ts[E + 1];
    __shared__ int s_cnt[E];

    int tid = threadIdx.x, w = tid >> 5, lane = tid & 31;
    if (tid == 0) {
        const int* cn = g_counts[layer & 1];
        int ts = 0;
#pragma unroll
        for (int e = 0; e < E; e++) {
            int c = cn[e];
            s_cnt[e] = c;
            s_ts[e] = ts;
            ts += (c + TM - 1) / TM;
        }
        s_ts[E] = ts;
    }
    __syncthreads();

    int gt = blockIdx.x;
    if (gt >= s_ts[E]) return;
    int part = blockIdx.y;
    int e = 0;
    while (gt >= s_ts[e + 1]) e++;
    int tile = gt - s_ts[e];
    int cnt  = s_cnt[e];

    if (tid < TM) {
        int idx = tile * TM + tid;
        s_tok[tid] = (idx < cnt) ? g_list[e * TOK + idx] : -1;
    }
    __syncthreads();

    int xr = tid >> 1, xc = (tid & 1) << 4;
    int xtok = s_tok[xr];
    int cx = (xtok >= 0) ? xtok : s_tok[0];
    const uint16_t* xhs = g_xh + (size_t)cx * H + part * KCH + xc;
    const uint16_t* xls = g_xl + (size_t)cx * H + part * KCH + xc;
    int ar = tid >> 2, ac = (tid & 3) << 3;
    size_t aoff = (((size_t)layer * E + e) * R + ar) * H + part * KCH + ac;
    const uint16_t* ahs = g_ah + aoff;
    const uint16_t* als = g_al + aoff;

    uint32_t sb = smem_u32(dsm);
    uint32_t xhd = sb + AP_XHI + xr * 80 + xc * 2;
    uint32_t xld = sb + AP_XLO + xr * 80 + xc * 2;
    uint32_t ahd = sb + AP_AHI + ar * 80 + ac * 2;
    uint32_t ald = sb + AP_ALO + ar * 80 + ac * 2;

#define ASTAGE(kb, soff) do {                                  \
        CP16(xhd + (soff),      xhs + (kb));                   \
        CP16(xhd + (soff) + 16, xhs + (kb) + 8);               \
        CP16(xld + (soff),      xls + (kb));                   \
        CP16(xld + (soff) + 16, xls + (kb) + 8);               \
        CP16(ahd + (soff),      ahs + (kb));                   \
        CP16(ald + (soff),      als + (kb));                   \
        CPCOMMIT();                                            \
    } while (0)

    ASTAGE(0, 0);
    ASTAGE(BK, AP_STG);

    int rin = lane & 7;
    int xrow = w * 16 + ((lane >> 3) & 1) * 8 + rin;
    int xko  = ((lane >> 4) & 1) * 8;
    int brow0 = ((lane >> 4) & 1) * 8 + rin;
    int bko   = ((lane >> 3) & 1) * 8;

    float acc[8][4];
#pragma unroll
    for (int nt = 0; nt < 8; nt++)
#pragma unroll
        for (int q = 0; q < 4; q++) acc[nt][q] = 0.f;

    int bufc = 0, bufs = 2;        // compute buf = kc%3, stage buf = (kc+2)%3
#pragma unroll 1
    for (int kc = 0; kc < NC; kc++) {
        CPWAIT1();                 // group kc complete
        __syncthreads();           // all warps done with chunk kc-1 (buf (kc+2)%3)
        if (kc + 2 < NC) ASTAGE((kc + 2) * BK, bufs * AP_STG);
        else CPCOMMIT();

        uint32_t stg = sb + bufc * AP_STG;
#pragma unroll
        for (int kh = 0; kh < 2; kh++) {
            uint32_t xh[4], xl[4];
            uint32_t ro = (uint32_t)xrow * 80 + (kh * 16 + xko) * 2;
            LDSM4(xh, stg + AP_XHI + ro);
            LDSM4(xl, stg + AP_XLO + ro);
            uint32_t bh[8][2], bl[8][2];
#pragma unroll
            for (int nj = 0; nj < 4; nj++) {
                uint32_t bo = (uint32_t)(brow0 + nj * 16) * 80 + (kh * 16 + bko) * 2;
                uint32_t r[4];
                LDSM4(r, stg + AP_AHI + bo);
                bh[nj*2][0] = r[0]; bh[nj*2][1] = r[1];
                bh[nj*2+1][0] = r[2]; bh[nj*2+1][1] = r[3];
                LDSM4(r, stg + AP_ALO + bo);
                bl[nj*2][0] = r[0]; bl[nj*2][1] = r[1];
                bl[nj*2+1][0] = r[2]; bl[nj*2+1][1] = r[3];
            }
#pragma unroll
            for (int nt = 0; nt < 8; nt++) {
                MMA(acc[nt], xh, bh[nt]);
                MMA(acc[nt], xh, bl[nt]);
                MMA(acc[nt], xl, bh[nt]);
            }
        }
        if (++bufc == 3) bufc = 0;
        if (++bufs == 3) bufs = 0;
    }
#undef ASTAGE

    float* hp = g_hpart[part];
    int mg = w * 16 + (lane >> 2);
    int t0 = s_tok[mg], t1 = s_tok[mg + 8];
#pragma unroll
    for (int nt = 0; nt < 8; nt++) {
        int n0 = nt * 8 + 2 * (lane & 3);
        if (t0 >= 0) *(float2*)&hp[(size_t)t0 * R + n0] = make_float2(acc[nt][0], acc[nt][1]);
        if (t1 >= 0) *(float2*)&hp[(size_t)t1 * R + n0] = make_float2(acc[nt][2], acc[nt][3]);
    }
}

// ---------------- reduce 4 partials -> bf16 hi/lo ------------------------------
__global__ void hreduce_kernel() {
    int i = blockIdx.x * 256 + threadIdx.x;
    float4 a = ((const float4*)g_hpart[0])[i];
    float4 b = ((const float4*)g_hpart[1])[i];
    float4 c = ((const float4*)g_hpart[2])[i];
    float4 d = ((const float4*)g_hpart[3])[i];
    float4 o;
    o.x = (a.x + b.x) + (c.x + d.x);
    o.y = (a.y + b.y) + (c.y + d.y);
    o.z = (a.z + b.z) + (c.z + d.z);
    o.w = (a.w + b.w) + (c.w + d.w);
    uint2 h, l;
    cvt_split(o.x, o.y, h.x, l.x);
    cvt_split(o.z, o.w, h.y, l.y);
    ((uint2*)g_hh)[i] = h;
    ((uint2*)g_hl)[i] = l;
}

// ---------------- B projection: NB=8 blocks/CTA, 3-stage single-sync ----------
__global__ void __launch_bounds__(256) bproj_kernel(int layer, float* __restrict__ y)
{
    extern __shared__ __align__(16) char dsm[];
    __shared__ int s_tok[TM];
    __shared__ int s_ts[E + 1];
    __shared__ int s_cnt[E];

    int tid = threadIdx.x, w = tid >> 5, lane = tid & 31;
    if (tid == 0) {
        const int* cn = g_counts[layer & 1];
        int ts = 0;
#pragma unroll
        for (int e = 0; e < E; e++) {
            int c = cn[e];
            s_cnt[e] = c;
            s_ts[e] = ts;
            ts += (c + TM - 1) / TM;
        }
        s_ts[E] = ts;
    }
    __syncthreads();

    int gt = blockIdx.x;
    if (gt >= s_ts[E]) return;
    int e = 0;
    while (gt >= s_ts[e + 1]) e++;
    int tile = gt - s_ts[e];
    int cnt  = s_cnt[e];
    int h0base = blockIdx.y * (64 * NB);

    if (tid < TM) {
        int idx = tile * TM + tid;
        s_tok[tid] = (idx < cnt) ? g_list[e * TOK + idx] : -1;
    }
    __syncthreads();

    uint32_t sb = smem_u32(dsm);

    int br = tid >> 2, bc = (tid & 3) << 4;
    size_t bbase = (((size_t)layer * E + e) * H + (size_t)h0base + br) * R + bc;

#define BSTAGE(nb, buf) do {                                                   \
        const uint16_t* bhs = g_bh + bbase + (size_t)(nb) * 64 * R;            \
        const uint16_t* bls = g_bl + bbase + (size_t)(nb) * 64 * R;            \
        uint32_t bd = sb + BPB(buf) + br * 144 + bc * 2;                       \
        CP16(bd,          bhs);                                                \
        CP16(bd + 16,     bhs + 8);                                            \
        CP16(bd + 9216,      bls);                                             \
        CP16(bd + 9216 + 16, bls + 8);                                         \
        CPCOMMIT();                                                            \
    } while (0)

    // stage H (once, in group with B block 0)
    {
        int hr = tid >> 1, hc = (tid & 1) << 5;
        int htok = s_tok[hr];
        int ct = (htok >= 0) ? htok : s_tok[0];
        const uint16_t* hhs = g_hh + (size_t)ct * R + hc;
        const uint16_t* hls = g_hl + (size_t)ct * R + hc;
        uint32_t hhd = sb + BPH_HI + hr * 144 + hc * 2;
        uint32_t hld = sb + BPH_LO + hr * 144 + hc * 2;
#pragma unroll
        for (int q = 0; q < 4; q++) {
            CP16(hhd + q * 16, hhs + q * 8);
            CP16(hld + q * 16, hls + q * 8);
        }
    }
    BSTAGE(0, 0);
    BSTAGE(1, 1);

    int rin = lane & 7;
    int xrow = w * 16 + ((lane >> 3) & 1) * 8 + rin;
    int xko  = ((lane >> 4) & 1) * 8;
    int brow0 = ((lane >> 4) & 1) * 8 + rin;
    int bko   = ((lane >> 3) & 1) * 8;

    int mg = w * 16 + (lane >> 2);
    int t0 = s_tok[mg], t1 = s_tok[mg + 8];
    float c0 = (t0 >= 0) ? g_coef[t0] : 0.f;
    float c1 = (t1 >= 0) ? g_coef[t1] : 0.f;

    int bufc = 0, bufs = 2;
#pragma unroll 1
    for (int nb = 0; nb < NB; nb++) {
        CPWAIT1();
        __syncthreads();
        if (nb + 2 < NB) BSTAGE(nb + 2, bufs);
        else CPCOMMIT();

        uint32_t bbuf = sb + BPB(bufc);

        float acc[8][4];
#pragma unroll
        for (int nt = 0; nt < 8; nt++)
#pragma unroll
            for (int q = 0; q < 4; q++) acc[nt][q] = 0.f;

#pragma unroll
        for (int kh = 0; kh < 4; kh++) {
            uint32_t xh[4], xl[4];
            uint32_t ro = (uint32_t)xrow * 144 + (kh * 16 + xko) * 2;
            LDSM4(xh, sb + BPH_HI + ro);
            LDSM4(xl, sb + BPH_LO + ro);
            uint32_t bh[8][2], bl[8][2];
#pragma unroll
            for (int nj = 0; nj < 4; nj++) {
                uint32_t bo = (uint32_t)(brow0 + nj * 16) * 144 + (kh * 16 + bko) * 2;
                uint32_t r[4];
                LDSM4(r, bbuf + bo);
                bh[nj*2][0] = r[0]; bh[nj*2][1] = r[1];
                bh[nj*2+1][0] = r[2]; bh[nj*2+1][1] = r[3];
                LDSM4(r, bbuf + 9216 + bo);
                bl[nj*2][0] = r[0]; bl[nj*2][1] = r[1];
                bl[nj*2+1][0] = r[2]; bl[nj*2+1][1] = r[3];
            }
#pragma unroll
            for (int nt = 0; nt < 8; nt++) {
                MMA(acc[nt], xh, bh[nt]);
                MMA(acc[nt], xh, bl[nt]);
                MMA(acc[nt], xl, bh[nt]);
            }
        }

        int h0 = h0base + nb * 64;
#pragma unroll
        for (int nt = 0; nt < 8; nt++) {
            int n0 = nt * 8 + 2 * (lane & 3);
            if (t0 >= 0)
                *(float2*)&y[(size_t)t0 * H + h0 + n0] =
                    make_float2(acc[nt][0] * c0, acc[nt][1] * c0);
            if (t1 >= 0)
                *(float2*)&y[(size_t)t1 * H + h0 + n0] =
                    make_float2(acc[nt][2] * c1, acc[nt][3] * c1);
        }
        if (++bufc == 3) bufc = 0;
        if (++bufs == 3) bufs = 0;
    }
#undef BSTAGE
}

// ---------------- launcher ------------------------------------------------------
extern "C" void kernel_launch(void* const* d_in, const int* in_sizes, int n_in,
                              void* d_out, int out_size)
{
    const float* hs    = (const float*)d_in[0];
    const float* gates = (const float*)d_in[1];
    const float* A     = (const float*)d_in[2];
    const float* Bm    = (const float*)d_in[3];
    const float* gw    = (const float*)d_in[4];
    float* y = (float*)d_out;

    const size_t HS = (size_t)TOK * H;
    const int ASM = AP_TOT;   // 92160
    const int BSM = BP_TOT;   // 92160

    cudaFuncSetAttribute(aproj_kernel, cudaFuncAttributeMaxDynamicSharedMemorySize, ASM);
    cudaFuncSetAttribute(bproj_kernel, cudaFuncAttributeMaxDynamicSharedMemorySize, BSM);
    cudaFuncSetAttribute(aproj_kernel, cudaFuncAttributePreferredSharedMemoryCarveout, 100);
    cudaFuncSetAttribute(bproj_kernel, cudaFuncAttributePreferredSharedMemoryCarveout, 100);

    wconv_kernel<<<(int)(2 * NWA / 4 / 256), 256>>>(A, Bm);
    for (int i = 0; i < L; i++) {
        const float* xprev = (i == 0) ? hs : y;
        const float* hx    = hs + (size_t)((i == 0) ? 1 : i) * HS;

        mix_gate_kernel<<<TOK / 8, 256>>>(xprev, hx, gw + (size_t)i * E * H, gates, i);
        aproj_kernel<<<dim3(NTILES, KSPLIT), 256, ASM>>>(i);
        hreduce_kernel<<<TOK * R / 4 / 256, 256>>>();
        bproj_kernel<<<dim3(NTILES, H / (64 * NB)), 256, BSM>>>(i, y);
    }
}